// round 17
// baseline (speedup 1.0000x reference)
#include <cuda_runtime.h>
#include <cuda_bf16.h>
#include <math.h>
#include <stdint.h>

// Problem constants (shapes fixed by the dataset).
#define DIM   256
#define MAXN  100000
#define MAXE  800000
#define CSRB  196           // csr_build blocks (all co-resident: 196 << capacity)
#define CSRT  512           // csr_build threads; CSRB*CSRT = 100352 >= MAXN

// -------- device-global scratch (allocation-free workaround) --------
__device__ float g_support[MAXN * DIM];   // x @ W
__device__ int   g_counts[MAXN];
__device__ int   g_scan[MAXN];            // per-chunk inclusive scan of counts
__device__ int   g_rowptr[MAXN + 1];
__device__ int   g_cursor[MAXN];
__device__ int   g_bsum[CSRB];            // per-chunk totals
__device__ int2  g_edge[MAXE];            // packed (src, val-bits) per edge
__device__ int   g_barc[4];               // spin-barrier counters (reset by GEMM)

// ---------------- fused CSR build (single kernel, device barriers) ----------
// 196 blocks x 512 thr, all resident -> spin barriers are deadlock-free.
__device__ __forceinline__ void grid_bar(int idx) {
    __syncthreads();
    if (threadIdx.x == 0) {
        __threadfence();
        atomicAdd(&g_barc[idx], 1);
        while (atomicAdd(&g_barc[idx], 0) < CSRB) { }
        __threadfence();
    }
    __syncthreads();
}

__global__ __launch_bounds__(CSRT) void k_csr_build(const int* __restrict__ dst,
                                                    const int* __restrict__ src,
                                                    const float* __restrict__ av,
                                                    const float* __restrict__ aw,
                                                    int n, int E) {
    // Let the (independent) GEMM secondary start immediately.
    cudaTriggerProgrammaticLaunchCompletion();

    const int tid = threadIdx.x;
    const int gt  = blockIdx.x * CSRT + tid;
    const int gth = CSRB * CSRT;
    __shared__ int s[CSRT];

    // phase 0: zero counts
    for (int i = gt; i < n; i += gth) g_counts[i] = 0;
    grid_bar(0);

    // phase 1: histogram of dst
    for (int e = gt; e < E; e += gth) atomicAdd(&g_counts[dst[e]], 1);
    grid_bar(1);

    // phase 2: per-chunk (512 rows) inclusive scan
    {
        int i = blockIdx.x * CSRT + tid;
        int v = (i < n) ? g_counts[i] : 0;
        s[tid] = v;
        __syncthreads();
        #pragma unroll
        for (int off = 1; off < CSRT; off <<= 1) {
            int x = (tid >= off) ? s[tid - off] : 0;
            __syncthreads();
            s[tid] += x;
            __syncthreads();
        }
        if (i < n) g_scan[i] = s[tid];
        if (tid == CSRT - 1) g_bsum[blockIdx.x] = s[tid];
    }
    grid_bar(2);

    // phase 3: every block redundantly scans the 196 chunk totals, then
    // finalizes rowptr + cursor for its own chunk.
    {
        int bv = (tid < CSRB) ? g_bsum[tid] : 0;
        s[tid] = bv;
        __syncthreads();
        #pragma unroll
        for (int off = 1; off < CSRT; off <<= 1) {
            int x = (tid >= off) ? s[tid - off] : 0;
            __syncthreads();
            s[tid] += x;
            __syncthreads();
        }
        int exb = s[blockIdx.x] - g_bsum[blockIdx.x];   // exclusive chunk offset
        int i = blockIdx.x * CSRT + tid;
        if (i < n) {
            g_rowptr[i + 1] = g_scan[i] + exb;
            g_cursor[i] = (tid == 0) ? exb : (g_scan[i - 1] + exb);
        }
        if (gt == 0) g_rowptr[0] = 0;
    }
    grid_bar(3);

    // phase 4: fill packed edges via atomic cursors
    for (int e = gt; e < E; e += gth) {
        int d = dst[e];
        int p = atomicAdd(&g_cursor[d], 1);
        g_edge[p] = make_int2(src[e], __float_as_int(av[e] + aw[e]));
    }
}

// ---------------- GEMM: support = x @ W  (3xBF16 tensor-core, FROZEN) ------
// 128x128 block tile, BK=32, 256 threads = 8 warps in 2(M) x 4(N).
// Measured: 180us, 127 regs, 2 CTAs/SM, tensor 41%.
// Block (0,0) pins kernel completion >= csr_build completion (griddepsync)
// and resets the csr barrier counters for the next replay.

__device__ __forceinline__ uint32_t pack_bf16(float a, float b) {
    __nv_bfloat162 h = __floats2bfloat162_rn(a, b);
    return *reinterpret_cast<uint32_t*>(&h);
}
__device__ __forceinline__ float bf16_hi_f(float a) {
    return __bfloat162float(__float2bfloat16_rn(a));
}

__device__ __forceinline__ void mma_bf16(float c[4], uint32_t a0, uint32_t a1,
                                         uint32_t a2, uint32_t a3,
                                         uint32_t b0, uint32_t b1) {
    asm volatile(
        "mma.sync.aligned.m16n8k16.row.col.f32.bf16.bf16.f32 "
        "{%0,%1,%2,%3}, {%4,%5,%6,%7}, {%8,%9}, {%0,%1,%2,%3};"
        : "+f"(c[0]), "+f"(c[1]), "+f"(c[2]), "+f"(c[3])
        : "r"(a0), "r"(a1), "r"(a2), "r"(a3), "r"(b0), "r"(b1));
}

#define GBM 128
#define GBN 128
#define GBK 32
#define KP  (GBK / 2)      // 16 k-pairs
#define A_PITCH 20         // u32 pitch ≡ 4 (mod 32): conflict-free A frag loads
#define B_PITCH 136       // u32 pitch ≡ 8 (mod 32): conflict-free B frag loads

__global__ __launch_bounds__(256) void k_gemm_bf16(const float* __restrict__ X,
                                                   const float* __restrict__ W, int Nrows) {
    __shared__ uint32_t Ash[GBM][A_PITCH];
    __shared__ uint32_t Asl[GBM][A_PITCH];
    __shared__ uint32_t Bsh[KP][B_PITCH];
    __shared__ uint32_t Bsl[KP][B_PITCH];

    const int tid  = threadIdx.x;
    const int lane = tid & 31;
    const int wid  = tid >> 5;
    const int warp_m = wid >> 2;        // 0..1
    const int warp_n = wid & 3;         // 0..3
    const int block_m = blockIdx.x * GBM;
    const int block_n = blockIdx.y * GBN;
    const int g  = lane >> 2;           // 0..7
    const int tg = lane & 3;            // 0..3

    float acc[4][4][4];
    #pragma unroll
    for (int i = 0; i < 4; i++)
        #pragma unroll
        for (int j = 0; j < 4; j++)
            #pragma unroll
            for (int r = 0; r < 4; r++) acc[i][j][r] = 0.0f;

    for (int k0 = 0; k0 < DIM; k0 += GBK) {
        #pragma unroll
        for (int l = 0; l < 4; l++) {
            int idx = tid + l * 256;        // 0..1023
            int r   = idx >> 3;             // 8 float4 per row
            int k4  = idx & 7;
            int grow = block_m + r;
            float4 a = make_float4(0.f, 0.f, 0.f, 0.f);
            if (grow < Nrows)
                a = *reinterpret_cast<const float4*>(&X[(size_t)grow * DIM + k0 + k4 * 4]);
            float hx = bf16_hi_f(a.x), hy = bf16_hi_f(a.y), hz = bf16_hi_f(a.z), hw = bf16_hi_f(a.w);
            Ash[r][2 * k4 + 0] = pack_bf16(hx, hy);
            Ash[r][2 * k4 + 1] = pack_bf16(hz, hw);
            Asl[r][2 * k4 + 0] = pack_bf16(a.x - hx, a.y - hy);
            Asl[r][2 * k4 + 1] = pack_bf16(a.z - hz, a.w - hw);
        }
        #pragma unroll
        for (int l = 0; l < 2; l++) {
            int idx = tid + l * 256;        // 0..511
            int kp  = idx >> 5;             // 0..15
            int n4  = idx & 31;
            float4 w0 = *reinterpret_cast<const float4*>(&W[(size_t)(k0 + 2 * kp)     * DIM + block_n + n4 * 4]);
            float4 w1 = *reinterpret_cast<const float4*>(&W[(size_t)(k0 + 2 * kp + 1) * DIM + block_n + n4 * 4]);
            float a0[4] = {w0.x, w0.y, w0.z, w0.w};
            float a1[4] = {w1.x, w1.y, w1.z, w1.w};
            #pragma unroll
            for (int j = 0; j < 4; j++) {
                float h0 = bf16_hi_f(a0[j]);
                float h1 = bf16_hi_f(a1[j]);
                Bsh[kp][n4 * 4 + j] = pack_bf16(h0, h1);
                Bsl[kp][n4 * 4 + j] = pack_bf16(a0[j] - h0, a1[j] - h1);
            }
        }
        __syncthreads();

        #pragma unroll
        for (int kc = 0; kc < KP; kc += 8) {   // two k16 chunks per BK=32
            uint32_t fah[4][4], fal[4][4];
            #pragma unroll
            for (int mt = 0; mt < 4; mt++) {
                int m = warp_m * 64 + mt * 16 + g;
                fah[mt][0] = Ash[m][kc + tg];
                fah[mt][1] = Ash[m + 8][kc + tg];
                fah[mt][2] = Ash[m][kc + tg + 4];
                fah[mt][3] = Ash[m + 8][kc + tg + 4];
                fal[mt][0] = Asl[m][kc + tg];
                fal[mt][1] = Asl[m + 8][kc + tg];
                fal[mt][2] = Asl[m][kc + tg + 4];
                fal[mt][3] = Asl[m + 8][kc + tg + 4];
            }
            uint32_t fbh[4][2], fbl[4][2];
            #pragma unroll
            for (int nt = 0; nt < 4; nt++) {
                int n = warp_n * 32 + nt * 8 + g;
                fbh[nt][0] = Bsh[kc + tg][n];
                fbh[nt][1] = Bsh[kc + tg + 4][n];
                fbl[nt][0] = Bsl[kc + tg][n];
                fbl[nt][1] = Bsl[kc + tg + 4][n];
            }
            #pragma unroll
            for (int mt = 0; mt < 4; mt++)
                #pragma unroll
                for (int nt = 0; nt < 4; nt++) {
                    mma_bf16(acc[mt][nt], fal[mt][0], fal[mt][1], fal[mt][2], fal[mt][3],
                             fbh[nt][0], fbh[nt][1]);
                    mma_bf16(acc[mt][nt], fah[mt][0], fah[mt][1], fah[mt][2], fah[mt][3],
                             fbl[nt][0], fbl[nt][1]);
                    mma_bf16(acc[mt][nt], fah[mt][0], fah[mt][1], fah[mt][2], fah[mt][3],
                             fbh[nt][0], fbh[nt][1]);
                }
        }
        __syncthreads();
    }

    #pragma unroll
    for (int mt = 0; mt < 4; mt++) {
        int r0 = block_m + warp_m * 64 + mt * 16 + g;
        #pragma unroll
        for (int nt = 0; nt < 4; nt++) {
            int c = block_n + warp_n * 32 + nt * 8 + 2 * tg;
            if (r0 < Nrows)
                *reinterpret_cast<float2*>(&g_support[(size_t)r0 * DIM + c]) =
                    make_float2(acc[mt][nt][0], acc[mt][nt][1]);
            if (r0 + 8 < Nrows)
                *reinterpret_cast<float2*>(&g_support[(size_t)(r0 + 8) * DIM + c]) =
                    make_float2(acc[mt][nt][2], acc[mt][nt][3]);
        }
    }

    // Pin GEMM completion >= csr_build completion; reset csr barriers.
    if (blockIdx.x == 0 && blockIdx.y == 0 && tid == 0) {
        cudaGridDependencySynchronize();
        #pragma unroll
        for (int k = 0; k < 4; k++) g_barc[k] = 0;
        __threadfence();
    }
}

// ---------------- SpMM + fused L2 normalize (warp-per-row, R14-proven) ----
__global__ __launch_bounds__(256) void k_spmm_norm(float* __restrict__ out, int n) {
    const int lane = threadIdx.x & 31;
    const int row  = blockIdx.x * 8 + (threadIdx.x >> 5);
    if (row >= n) return;

    const int beg = g_rowptr[row];
    const int end = g_rowptr[row + 1];

    float4 p0 = make_float4(0.f, 0.f, 0.f, 0.f);
    float4 p1 = make_float4(0.f, 0.f, 0.f, 0.f);
    float4 q0 = make_float4(0.f, 0.f, 0.f, 0.f);
    float4 q1 = make_float4(0.f, 0.f, 0.f, 0.f);

    int e = beg;
    for (; e + 1 < end; e += 2) {
        int2 e0 = __ldg(&g_edge[e]);
        int2 e1 = __ldg(&g_edge[e + 1]);
        int   s0 = e0.x;
        int   s1 = e1.x;
        float v0 = __int_as_float(e0.y);
        float v1 = __int_as_float(e1.y);
        const float4* r0 = reinterpret_cast<const float4*>(&g_support[(size_t)s0 * DIM]);
        const float4* r1 = reinterpret_cast<const float4*>(&g_support[(size_t)s1 * DIM]);
        float4 x0 = r0[lane];
        float4 x1 = r0[lane + 32];
        float4 y0 = r1[lane];
        float4 y1 = r1[lane + 32];
        p0.x = fmaf(v0, x0.x, p0.x); p0.y = fmaf(v0, x0.y, p0.y);
        p0.z = fmaf(v0, x0.z, p0.z); p0.w = fmaf(v0, x0.w, p0.w);
        p1.x = fmaf(v0, x1.x, p1.x); p1.y = fmaf(v0, x1.y, p1.y);
        p1.z = fmaf(v0, x1.z, p1.z); p1.w = fmaf(v0, x1.w, p1.w);
        q0.x = fmaf(v1, y0.x, q0.x); q0.y = fmaf(v1, y0.y, q0.y);
        q0.z = fmaf(v1, y0.z, q0.z); q0.w = fmaf(v1, y0.w, q0.w);
        q1.x = fmaf(v1, y1.x, q1.x); q1.y = fmaf(v1, y1.y, q1.y);
        q1.z = fmaf(v1, y1.z, q1.z); q1.w = fmaf(v1, y1.w, q1.w);
    }
    if (e < end) {
        int2 e0 = __ldg(&g_edge[e]);
        int   s0 = e0.x;
        float v0 = __int_as_float(e0.y);
        const float4* r0 = reinterpret_cast<const float4*>(&g_support[(size_t)s0 * DIM]);
        float4 x0 = r0[lane];
        float4 x1 = r0[lane + 32];
        p0.x = fmaf(v0, x0.x, p0.x); p0.y = fmaf(v0, x0.y, p0.y);
        p0.z = fmaf(v0, x0.z, p0.z); p0.w = fmaf(v0, x0.w, p0.w);
        p1.x = fmaf(v0, x1.x, p1.x); p1.y = fmaf(v0, x1.y, p1.y);
        p1.z = fmaf(v0, x1.z, p1.z); p1.w = fmaf(v0, x1.w, p1.w);
    }
    float4 a0 = make_float4(p0.x + q0.x, p0.y + q0.y, p0.z + q0.z, p0.w + q0.w);
    float4 a1 = make_float4(p1.x + q1.x, p1.y + q1.y, p1.z + q1.z, p1.w + q1.w);

    float ss = a0.x * a0.x + a0.y * a0.y + a0.z * a0.z + a0.w * a0.w
             + a1.x * a1.x + a1.y * a1.y + a1.z * a1.z + a1.w * a1.w;
    #pragma unroll
    for (int o = 16; o > 0; o >>= 1)
        ss += __shfl_xor_sync(0xFFFFFFFF, ss, o);

    float inv = 1.0f / fmaxf(sqrtf(ss), 1e-12f);
    float4* dst = reinterpret_cast<float4*>(&out[(size_t)row * DIM]);
    dst[lane]      = make_float4(a0.x * inv, a0.y * inv, a0.z * inv, a0.w * inv);
    dst[lane + 32] = make_float4(a1.x * inv, a1.y * inv, a1.z * inv, a1.w * inv);
}

// ---------------- launch ----------------
extern "C" void kernel_launch(void* const* d_in, const int* in_sizes, int n_in,
                              void* d_out, int out_size) {
    const float* x  = (const float*)d_in[0];   // [N, 256]
    const float* W  = (const float*)d_in[1];   // [256, 256]
    const float* av = (const float*)d_in[2];   // [E]
    const float* aw = (const float*)d_in[3];   // [E]
    const int*   ei = (const int*)  d_in[4];   // [2, E]: dst row, then src row
    float* out = (float*)d_out;

    int N = in_sizes[0] / DIM;
    int E = in_sizes[2];
    const int* dst = ei;
    const int* src = ei + E;

    // 1. Fused CSR build (primary of the PDL pair).
    k_csr_build<<<CSRB, CSRT>>>(dst, src, av, aw, N, E);

    // 2. GEMM as PDL secondary: starts while csr_build runs (independent work).
    dim3 ggrid((N + GBM - 1) / GBM, DIM / GBN);
    {
        cudaLaunchConfig_t cfg = {};
        cfg.gridDim  = ggrid;
        cfg.blockDim = dim3(256, 1, 1);
        cudaLaunchAttribute at[1];
        at[0].id = cudaLaunchAttributeProgrammaticStreamSerialization;
        at[0].val.programmaticStreamSerializationAllowed = 1;
        cfg.attrs = at;
        cfg.numAttrs = 1;
        cudaError_t err = cudaLaunchKernelEx(&cfg, k_gemm_bf16, x, W, N);
        if (err != cudaSuccess) {
            // Fallback: plain serialized launch (correct, just no overlap).
            k_gemm_bf16<<<ggrid, 256>>>(x, W, N);
        }
    }

    // 3. SpMM + normalize. Full-completion edge to GEMM; GEMM's griddepsync
    //    transitively guarantees csr_build (rowptr/edges) is complete too.
    k_spmm_norm<<<(N + 7) / 8, 256>>>(out, N);
}